// round 5
// baseline (speedup 1.0000x reference)
#include <cuda_runtime.h>

// Problem constants
#define BATCH   64
#define TSTEPS  512
#define IN_DIM  1024
#define HID     1024
#define MTOT    (BATCH * TSTEPS)           // 32768 rows of the GEMM

// ALPHA = exp(-1/20) rounded to fp32
#define ALPHA_F 0.95122942450071400909f

// Scratch for the synaptic currents I[b,t,h] (128 MiB).
__device__ float g_I[(size_t)MTOT * HID];

// Packed dual-FMA: d.lo = rn(a.lo*b.lo + c.lo), d.hi = rn(a.hi*b.hi + c.hi)
// Bitwise identical to two scalar fmaf's. SASS: FFMA2 (sm_10x only).
__device__ __forceinline__ unsigned long long fma2(unsigned long long a,
                                                   unsigned long long b,
                                                   unsigned long long c)
{
    unsigned long long d;
    asm("fma.rn.f32x2 %0, %1, %2, %3;" : "=l"(d) : "l"(a), "l"(b), "l"(c));
    return d;
}

__device__ __forceinline__ unsigned long long bcast2(float x)
{
    unsigned int xi = __float_as_uint(x);
    unsigned long long d;
    asm("mov.b64 %0, {%1, %1};" : "=l"(d) : "r"(xi));
    return d;
}

// ---------------------------------------------------------------------------
// GEMM: g_I[m, n] = sum_k x[m, k] * W[n, k]  + b[n]
// Strictly in-order ascending-k accumulation per output, FMA each step
// (bit-exact vs reference). Packed f32x2: two outputs (adjacent n) per
// instruction — per-lane rounding identical to scalar.
// 128x128 tile, BK=16, 256 threads, 4x16 microtile.
// ROUND 4: no min-blocks reg cap (spill fix); double-buffered smem with
// register prefetch pipeline (1 sync/iter) to hide global latency at 1 CTA/SM.
// ---------------------------------------------------------------------------
#define BM 128
#define BN 128
#define BK 16

__global__ __launch_bounds__(256)
void snn_gemm_kernel(const float* __restrict__ A,      // x  [MTOT, IN_DIM]
                     const float* __restrict__ Wt,     // W  [HID, IN_DIM]
                     const float* __restrict__ bias)   // b  [HID]
{
    __shared__ float As[2][BK][BM];   // As[buf][k][m]
    __shared__ float Bs[2][BK][BN];   // Bs[buf][k][n]

    const int tid  = threadIdx.x;          // 0..255
    const int tx   = tid & 7;              // col group: 16 cols each
    const int ty   = tid >> 3;             // row group: 4 rows each (0..31)
    const int row0 = blockIdx.y * BM;
    const int col0 = blockIdx.x * BN;

    // Cooperative-load geometry: this thread owns float4 slots f=tid, tid+256.
    const int ra = tid >> 2;               // row for slot 0 (0..63)
    const int rb = ra + 64;                // row for slot 1 (64..127)
    const int ck = (tid & 3) * 4;          // k offset within tile

    const float* pa0 = A  + (size_t)(row0 + ra) * IN_DIM + ck;
    const float* pa1 = A  + (size_t)(row0 + rb) * IN_DIM + ck;
    const float* pw0 = Wt + (size_t)(col0 + ra) * IN_DIM + ck;
    const float* pw1 = Wt + (size_t)(col0 + rb) * IN_DIM + ck;

    unsigned long long acc2[4][8];
#pragma unroll
    for (int i = 0; i < 4; i++)
#pragma unroll
        for (int j = 0; j < 8; j++) acc2[i][j] = 0ull;

    // Prologue: load tile 0 and stage into buffer 0.
    {
        float4 av0 = *reinterpret_cast<const float4*>(pa0);
        float4 av1 = *reinterpret_cast<const float4*>(pa1);
        float4 wv0 = *reinterpret_cast<const float4*>(pw0);
        float4 wv1 = *reinterpret_cast<const float4*>(pw1);
        As[0][ck + 0][ra] = av0.x; As[0][ck + 1][ra] = av0.y;
        As[0][ck + 2][ra] = av0.z; As[0][ck + 3][ra] = av0.w;
        As[0][ck + 0][rb] = av1.x; As[0][ck + 1][rb] = av1.y;
        As[0][ck + 2][rb] = av1.z; As[0][ck + 3][rb] = av1.w;
        Bs[0][ck + 0][ra] = wv0.x; Bs[0][ck + 1][ra] = wv0.y;
        Bs[0][ck + 2][ra] = wv0.z; Bs[0][ck + 3][ra] = wv0.w;
        Bs[0][ck + 0][rb] = wv1.x; Bs[0][ck + 1][rb] = wv1.y;
        Bs[0][ck + 2][rb] = wv1.z; Bs[0][ck + 3][rb] = wv1.w;
    }
    __syncthreads();

    int cur = 0;
    for (int k0 = 0; k0 < IN_DIM; k0 += BK) {
        const bool has_next = (k0 + BK) < IN_DIM;

        // Prefetch next tile into registers (latency hidden by compute below).
        float4 av0, av1, wv0, wv1;
        if (has_next) {
            const int ko = k0 + BK;
            av0 = *reinterpret_cast<const float4*>(pa0 + ko);
            av1 = *reinterpret_cast<const float4*>(pa1 + ko);
            wv0 = *reinterpret_cast<const float4*>(pw0 + ko);
            wv1 = *reinterpret_cast<const float4*>(pw1 + ko);
        }

#pragma unroll
        for (int kk = 0; kk < BK; kk++) {
            // a: 4 rows, broadcast each into both halves of a pair
            float a[4];
            *reinterpret_cast<float4*>(a) =
                *reinterpret_cast<const float4*>(&As[cur][kk][ty * 4]);
            unsigned long long aa[4];
#pragma unroll
            for (int i = 0; i < 4; i++) aa[i] = bcast2(a[i]);

            // b: 16 cols = 8 lane pairs, already adjacent in shared
            unsigned long long bb[8];
            ulonglong2 t0 = *reinterpret_cast<const ulonglong2*>(&Bs[cur][kk][tx * 16 + 0]);
            ulonglong2 t1 = *reinterpret_cast<const ulonglong2*>(&Bs[cur][kk][tx * 16 + 4]);
            ulonglong2 t2 = *reinterpret_cast<const ulonglong2*>(&Bs[cur][kk][tx * 16 + 8]);
            ulonglong2 t3 = *reinterpret_cast<const ulonglong2*>(&Bs[cur][kk][tx * 16 + 12]);
            bb[0] = t0.x; bb[1] = t0.y; bb[2] = t1.x; bb[3] = t1.y;
            bb[4] = t2.x; bb[5] = t2.y; bb[6] = t3.x; bb[7] = t3.y;

#pragma unroll
            for (int i = 0; i < 4; i++)
#pragma unroll
                for (int j = 0; j < 8; j++)
                    acc2[i][j] = fma2(aa[i], bb[j], acc2[i][j]);
        }

        if (has_next) {
            const int nxt = cur ^ 1;
            As[nxt][ck + 0][ra] = av0.x; As[nxt][ck + 1][ra] = av0.y;
            As[nxt][ck + 2][ra] = av0.z; As[nxt][ck + 3][ra] = av0.w;
            As[nxt][ck + 0][rb] = av1.x; As[nxt][ck + 1][rb] = av1.y;
            As[nxt][ck + 2][rb] = av1.z; As[nxt][ck + 3][rb] = av1.w;
            Bs[nxt][ck + 0][ra] = wv0.x; Bs[nxt][ck + 1][ra] = wv0.y;
            Bs[nxt][ck + 2][ra] = wv0.z; Bs[nxt][ck + 3][ra] = wv0.w;
            Bs[nxt][ck + 0][rb] = wv1.x; Bs[nxt][ck + 1][rb] = wv1.y;
            Bs[nxt][ck + 2][rb] = wv1.z; Bs[nxt][ck + 3][rb] = wv1.w;
        }
        __syncthreads();
        cur ^= 1;
    }

    // Bias: single rounded add after the full K sum (matches "einsum + b").
#pragma unroll
    for (int i = 0; i < 4; i++) {
        const int r = row0 + ty * 4 + i;
#pragma unroll
        for (int j = 0; j < 8; j += 2) {
            const int c = col0 + tx * 16 + j * 2;
            float2 p0 = *reinterpret_cast<float2*>(&acc2[i][j + 0]);
            float2 p1 = *reinterpret_cast<float2*>(&acc2[i][j + 1]);
            float4 o;
            o.x = __fadd_rn(p0.x, bias[c + 0]);
            o.y = __fadd_rn(p0.y, bias[c + 1]);
            o.z = __fadd_rn(p1.x, bias[c + 2]);
            o.w = __fadd_rn(p1.y, bias[c + 3]);
            *reinterpret_cast<float4*>(&g_I[(size_t)r * HID + c]) = o;
        }
    }
}

// ---------------------------------------------------------------------------
// LIF scan: one thread per (b, h) neuron, sequential over t.
// mem = fma.rn(alpha, mem, I); spike = (mem >= 1); hard reset.
// Unroll 16 for MLP=16 (latency-bound: only 65536 threads exist).
// ---------------------------------------------------------------------------
__global__ __launch_bounds__(128)
void snn_scan_kernel(float* __restrict__ spikes,     // [B, T, H]
                     float* __restrict__ mem_final)  // [B, H]
{
    const int idx = blockIdx.x * blockDim.x + threadIdx.x;   // 0..65535
    const int b = idx >> 10;          // / HID
    const int h = idx & (HID - 1);

    const float* ip = g_I + (size_t)b * TSTEPS * HID + h;
    float* sp = spikes + (size_t)b * TSTEPS * HID + h;

    float mem = 0.0f;
    for (int t0 = 0; t0 < TSTEPS; t0 += 16) {
        float cur[16];
#pragma unroll
        for (int u = 0; u < 16; u++)
            cur[u] = __ldcg(ip + (size_t)(t0 + u) * HID);

        float sv[16];
#pragma unroll
        for (int u = 0; u < 16; u++) {
            mem = fmaf(ALPHA_F, mem, cur[u]);    // fused: one rounding
            const bool fire = (mem >= 1.0f);
            sv[u] = fire ? 1.0f : 0.0f;
            if (fire) mem = 0.0f;
        }
#pragma unroll
        for (int u = 0; u < 16; u++)
            sp[(size_t)(t0 + u) * HID] = sv[u];
    }
    mem_final[idx] = mem;
}

// ---------------------------------------------------------------------------
// Launch
// ---------------------------------------------------------------------------
extern "C" void kernel_launch(void* const* d_in, const int* in_sizes, int n_in,
                              void* d_out, int out_size)
{
    const float* x = (const float*)d_in[0];   // [B, T, IN_DIM]
    const float* W = (const float*)d_in[1];   // [HID, IN_DIM]
    const float* b = (const float*)d_in[2];   // [HID]

    float* out        = (float*)d_out;
    float* spikes     = out;                                  // [B, T, H]
    float* mem_final  = out + (size_t)BATCH * TSTEPS * HID;   // [B, H]

    dim3 ggrid(HID / BN, MTOT / BM);    // (8, 256)
    snn_gemm_kernel<<<ggrid, 256>>>(x, W, b);

    snn_scan_kernel<<<(BATCH * HID) / 128, 128>>>(spikes, mem_final);
}

// round 6
// speedup vs baseline: 2.8878x; 2.8878x over previous
#include <cuda_runtime.h>

// Problem constants
#define BATCH   64
#define TSTEPS  512
#define IN_DIM  1024
#define HID     1024
#define MTOT    (BATCH * TSTEPS)           // 32768 rows of the GEMM

// ALPHA = exp(-1/20) rounded to fp32
#define ALPHA_F 0.95122942450071400909f

// Scratch for the synaptic currents I[b,t,h] (128 MiB).
__device__ float g_I[(size_t)MTOT * HID];

// ---------------------------------------------------------------------------
// GEMM: g_I[m, n] = sum_k x[m, k] * W[n, k]  + b[n]
// Strictly in-order ascending-k accumulation, single fp32 accumulator, scalar
// FMA (bit-exact vs reference; FFMA already issues at full rate — f32x2 was
// falsified twice).
// 128x128 tile, BK=16, 256 threads, 8x8 microtile, 2 CTAs/SM.
// ROUND 6: double-buffered smem + register prefetch, 1 sync/iter.
// ---------------------------------------------------------------------------
#define BM 128
#define BN 128
#define BK 16

__global__ __launch_bounds__(256, 2)
void snn_gemm_kernel(const float* __restrict__ A,      // x  [MTOT, IN_DIM]
                     const float* __restrict__ Wt,     // W  [HID, IN_DIM]
                     const float* __restrict__ bias)   // b  [HID]
{
    __shared__ float As[2][BK][BM];   // As[buf][k][m]
    __shared__ float Bs[2][BK][BN];   // Bs[buf][k][n]

    const int tid  = threadIdx.x;          // 0..255
    const int tx   = tid & 15;             // col group: 8 cols each
    const int ty   = tid >> 4;             // row group: 8 rows each
    const int row0 = blockIdx.y * BM;
    const int col0 = blockIdx.x * BN;

    // Cooperative-load geometry: this thread owns float4 slots f=tid, tid+256.
    const int ra = tid >> 2;               // row for slot 0 (0..63)
    const int rb = ra + 64;                // row for slot 1 (64..127)
    const int ck = (tid & 3) * 4;          // k offset within tile

    const float* pa0 = A  + (size_t)(row0 + ra) * IN_DIM + ck;
    const float* pa1 = A  + (size_t)(row0 + rb) * IN_DIM + ck;
    const float* pw0 = Wt + (size_t)(col0 + ra) * IN_DIM + ck;
    const float* pw1 = Wt + (size_t)(col0 + rb) * IN_DIM + ck;

    float acc[8][8];
#pragma unroll
    for (int i = 0; i < 8; i++)
#pragma unroll
        for (int j = 0; j < 8; j++) acc[i][j] = 0.0f;

    // Prologue: load tile 0 into buffer 0.
    {
        float4 av0 = *reinterpret_cast<const float4*>(pa0);
        float4 av1 = *reinterpret_cast<const float4*>(pa1);
        float4 wv0 = *reinterpret_cast<const float4*>(pw0);
        float4 wv1 = *reinterpret_cast<const float4*>(pw1);
        As[0][ck + 0][ra] = av0.x; As[0][ck + 1][ra] = av0.y;
        As[0][ck + 2][ra] = av0.z; As[0][ck + 3][ra] = av0.w;
        As[0][ck + 0][rb] = av1.x; As[0][ck + 1][rb] = av1.y;
        As[0][ck + 2][rb] = av1.z; As[0][ck + 3][rb] = av1.w;
        Bs[0][ck + 0][ra] = wv0.x; Bs[0][ck + 1][ra] = wv0.y;
        Bs[0][ck + 2][ra] = wv0.z; Bs[0][ck + 3][ra] = wv0.w;
        Bs[0][ck + 0][rb] = wv1.x; Bs[0][ck + 1][rb] = wv1.y;
        Bs[0][ck + 2][rb] = wv1.z; Bs[0][ck + 3][rb] = wv1.w;
    }
    __syncthreads();

    int cur = 0;
    for (int k0 = 0; k0 < IN_DIM; k0 += BK) {
        const bool has_next = (k0 + BK) < IN_DIM;

        // Prefetch next tile into registers; latency hidden by the 16-step
        // compute phase below.
        float4 av0, av1, wv0, wv1;
        if (has_next) {
            const int ko = k0 + BK;
            av0 = *reinterpret_cast<const float4*>(pa0 + ko);
            av1 = *reinterpret_cast<const float4*>(pa1 + ko);
            wv0 = *reinterpret_cast<const float4*>(pw0 + ko);
            wv1 = *reinterpret_cast<const float4*>(pw1 + ko);
        }

#pragma unroll
        for (int kk = 0; kk < BK; kk++) {
            float a[8], b[8];
            *reinterpret_cast<float4*>(&a[0]) =
                *reinterpret_cast<const float4*>(&As[cur][kk][ty * 8]);
            *reinterpret_cast<float4*>(&a[4]) =
                *reinterpret_cast<const float4*>(&As[cur][kk][ty * 8 + 4]);
            *reinterpret_cast<float4*>(&b[0]) =
                *reinterpret_cast<const float4*>(&Bs[cur][kk][tx * 8]);
            *reinterpret_cast<float4*>(&b[4]) =
                *reinterpret_cast<const float4*>(&Bs[cur][kk][tx * 8 + 4]);
#pragma unroll
            for (int i = 0; i < 8; i++)
#pragma unroll
                for (int j = 0; j < 8; j++)
                    acc[i][j] = fmaf(a[i], b[j], acc[i][j]);
        }

        if (has_next) {
            const int nxt = cur ^ 1;
            As[nxt][ck + 0][ra] = av0.x; As[nxt][ck + 1][ra] = av0.y;
            As[nxt][ck + 2][ra] = av0.z; As[nxt][ck + 3][ra] = av0.w;
            As[nxt][ck + 0][rb] = av1.x; As[nxt][ck + 1][rb] = av1.y;
            As[nxt][ck + 2][rb] = av1.z; As[nxt][ck + 3][rb] = av1.w;
            Bs[nxt][ck + 0][ra] = wv0.x; Bs[nxt][ck + 1][ra] = wv0.y;
            Bs[nxt][ck + 2][ra] = wv0.z; Bs[nxt][ck + 3][ra] = wv0.w;
            Bs[nxt][ck + 0][rb] = wv1.x; Bs[nxt][ck + 1][rb] = wv1.y;
            Bs[nxt][ck + 2][rb] = wv1.z; Bs[nxt][ck + 3][rb] = wv1.w;
        }
        __syncthreads();
        cur ^= 1;
    }

    // Bias: single rounded add after the full K sum (matches "einsum + b").
#pragma unroll
    for (int i = 0; i < 8; i++) {
        const int r = row0 + ty * 8 + i;
#pragma unroll
        for (int j = 0; j < 8; j += 4) {
            const int c = col0 + tx * 8 + j;
            float4 o;
            o.x = __fadd_rn(acc[i][j + 0], bias[c + 0]);
            o.y = __fadd_rn(acc[i][j + 1], bias[c + 1]);
            o.z = __fadd_rn(acc[i][j + 2], bias[c + 2]);
            o.w = __fadd_rn(acc[i][j + 3], bias[c + 3]);
            *reinterpret_cast<float4*>(&g_I[(size_t)r * HID + c]) = o;
        }
    }
}

// ---------------------------------------------------------------------------
// LIF scan: one thread per (b, h) neuron, sequential over t.
// mem = fma.rn(alpha, mem, I); spike = (mem >= 1); hard reset.
// Unroll 16 for MLP=16.
// ---------------------------------------------------------------------------
__global__ __launch_bounds__(128)
void snn_scan_kernel(float* __restrict__ spikes,     // [B, T, H]
                     float* __restrict__ mem_final)  // [B, H]
{
    const int idx = blockIdx.x * blockDim.x + threadIdx.x;   // 0..65535
    const int b = idx >> 10;          // / HID
    const int h = idx & (HID - 1);

    const float* ip = g_I + (size_t)b * TSTEPS * HID + h;
    float* sp = spikes + (size_t)b * TSTEPS * HID + h;

    float mem = 0.0f;
    for (int t0 = 0; t0 < TSTEPS; t0 += 16) {
        float cur[16];
#pragma unroll
        for (int u = 0; u < 16; u++)
            cur[u] = __ldcg(ip + (size_t)(t0 + u) * HID);

        float sv[16];
#pragma unroll
        for (int u = 0; u < 16; u++) {
            mem = fmaf(ALPHA_F, mem, cur[u]);    // fused: one rounding
            const bool fire = (mem >= 1.0f);
            sv[u] = fire ? 1.0f : 0.0f;
            if (fire) mem = 0.0f;
        }
#pragma unroll
        for (int u = 0; u < 16; u++)
            sp[(size_t)(t0 + u) * HID] = sv[u];
    }
    mem_final[idx] = mem;
}

// ---------------------------------------------------------------------------
// Launch
// ---------------------------------------------------------------------------
extern "C" void kernel_launch(void* const* d_in, const int* in_sizes, int n_in,
                              void* d_out, int out_size)
{
    const float* x = (const float*)d_in[0];   // [B, T, IN_DIM]
    const float* W = (const float*)d_in[1];   // [HID, IN_DIM]
    const float* b = (const float*)d_in[2];   // [HID]

    float* out        = (float*)d_out;
    float* spikes     = out;                                  // [B, T, H]
    float* mem_final  = out + (size_t)BATCH * TSTEPS * HID;   // [B, H]

    dim3 ggrid(HID / BN, MTOT / BM);    // (8, 256)
    snn_gemm_kernel<<<ggrid, 256>>>(x, W, b);

    snn_scan_kernel<<<(BATCH * HID) / 128, 128>>>(spikes, mem_final);
}

// round 9
// speedup vs baseline: 3.4508x; 1.1949x over previous
#include <cuda_runtime.h>

// Problem constants
#define BATCH   64
#define TSTEPS  512
#define IN_DIM  1024
#define HID     1024
#define MTOT    (BATCH * TSTEPS)           // 32768 rows of the GEMM

// ALPHA = exp(-1/20) rounded to fp32
#define ALPHA_F 0.95122942450071400909f

// Scratch for the synaptic currents I[b,t,h] (128 MiB).
__device__ float g_I[(size_t)MTOT * HID];

// ---------------------------------------------------------------------------
// GEMM: g_I[m, n] = sum_k x[m, k] * W[n, k]  + b[n]
// Strictly in-order ascending-k accumulation, single fp32 accumulator, scalar
// FMA (bit-exact vs reference).
// 128x128 tile, BK=16, 256 threads, 16x4 microtile (warp=16 rows, lane=4 cols)
// ROUND 7: XOR-swizzled smem (col ^ ((k>>2&3)*8)) -> conflict-free STS and
// LDS; b-fragment is one contiguous LDS.128 per kk; a-fragment is broadcast.
// Double-buffered smem + register prefetch, 1 sync/iter, 2 CTAs/SM.
// ---------------------------------------------------------------------------
#define BM 128
#define BN 128
#define BK 16

__global__ __launch_bounds__(256, 2)
void snn_gemm_kernel(const float* __restrict__ A,      // x  [MTOT, IN_DIM]
                     const float* __restrict__ Wt,     // W  [HID, IN_DIM]
                     const float* __restrict__ bias)   // b  [HID]
{
    __shared__ float As[2][BK][BM];   // element (k,m) at As[buf][k][m ^ swz(k)]
    __shared__ float Bs[2][BK][BN];   // element (k,n) at Bs[buf][k][n ^ swz(k)]
    // swz(k) = ((k>>2)&3)*8

    const int tid  = threadIdx.x;          // 0..255
    const int lane = tid & 31;             // 4 cols each: cols lane*4..+3
    const int w    = tid >> 5;             // warp: 16 rows each
    const int row0 = blockIdx.y * BM;
    const int col0 = blockIdx.x * BN;

    // Cooperative-load geometry: thread owns float4 slots f=tid, tid+256.
    const int ra = tid >> 2;               // row for slot 0 (0..63)
    const int rb = ra + 64;                // row for slot 1 (64..127)
    const int ck = (tid & 3) * 4;          // k offset within tile
    const int swz_st = (tid & 3) * 8;      // store swizzle = ((ck>>2)&3)*8
    const int ca = ra ^ swz_st;            // swizzled store col, slot 0
    const int cb = rb ^ swz_st;            // swizzled store col, slot 1

    const float* pa0 = A  + (size_t)(row0 + ra) * IN_DIM + ck;
    const float* pa1 = A  + (size_t)(row0 + rb) * IN_DIM + ck;
    const float* pw0 = Wt + (size_t)(col0 + ra) * IN_DIM + ck;
    const float* pw1 = Wt + (size_t)(col0 + rb) * IN_DIM + ck;

    float acc[16][4];
#pragma unroll
    for (int i = 0; i < 16; i++)
#pragma unroll
        for (int j = 0; j < 4; j++) acc[i][j] = 0.0f;

    // Prologue: load tile 0 into buffer 0 (swizzled scatter, conflict-free).
    {
        float4 av0 = *reinterpret_cast<const float4*>(pa0);
        float4 av1 = *reinterpret_cast<const float4*>(pa1);
        float4 wv0 = *reinterpret_cast<const float4*>(pw0);
        float4 wv1 = *reinterpret_cast<const float4*>(pw1);
        As[0][ck + 0][ca] = av0.x; As[0][ck + 1][ca] = av0.y;
        As[0][ck + 2][ca] = av0.z; As[0][ck + 3][ca] = av0.w;
        As[0][ck + 0][cb] = av1.x; As[0][ck + 1][cb] = av1.y;
        As[0][ck + 2][cb] = av1.z; As[0][ck + 3][cb] = av1.w;
        Bs[0][ck + 0][ca] = wv0.x; Bs[0][ck + 1][ca] = wv0.y;
        Bs[0][ck + 2][ca] = wv0.z; Bs[0][ck + 3][ca] = wv0.w;
        Bs[0][ck + 0][cb] = wv1.x; Bs[0][ck + 1][cb] = wv1.y;
        Bs[0][ck + 2][cb] = wv1.z; Bs[0][ck + 3][cb] = wv1.w;
    }
    __syncthreads();

    int cur = 0;
    for (int k0 = 0; k0 < IN_DIM; k0 += BK) {
        const bool has_next = (k0 + BK) < IN_DIM;

        // Prefetch next tile into registers.
        float4 av0, av1, wv0, wv1;
        if (has_next) {
            const int ko = k0 + BK;
            av0 = *reinterpret_cast<const float4*>(pa0 + ko);
            av1 = *reinterpret_cast<const float4*>(pa1 + ko);
            wv0 = *reinterpret_cast<const float4*>(pw0 + ko);
            wv1 = *reinterpret_cast<const float4*>(pw1 + ko);
        }

#pragma unroll
        for (int kk = 0; kk < BK; kk++) {
            const int swzk = ((kk >> 2) & 3) * 8;   // compile-time in unroll

            // b: one contiguous (permuted) LDS.128 — conflict-free
            float b[4];
            *reinterpret_cast<float4*>(b) =
                *reinterpret_cast<const float4*>(&Bs[cur][kk][(lane * 4) ^ swzk]);

            // a: 4 broadcast LDS.128 (all lanes same address)
            float a[16];
#pragma unroll
            for (int q = 0; q < 4; q++)
                *reinterpret_cast<float4*>(&a[q * 4]) =
                    *reinterpret_cast<const float4*>(&As[cur][kk][(w * 16 + q * 4) ^ swzk]);

#pragma unroll
            for (int i = 0; i < 16; i++)
#pragma unroll
                for (int j = 0; j < 4; j++)
                    acc[i][j] = fmaf(a[i], b[j], acc[i][j]);
        }

        if (has_next) {
            const int nxt = cur ^ 1;
            As[nxt][ck + 0][ca] = av0.x; As[nxt][ck + 1][ca] = av0.y;
            As[nxt][ck + 2][ca] = av0.z; As[nxt][ck + 3][ca] = av0.w;
            As[nxt][ck + 0][cb] = av1.x; As[nxt][ck + 1][cb] = av1.y;
            As[nxt][ck + 2][cb] = av1.z; As[nxt][ck + 3][cb] = av1.w;
            Bs[nxt][ck + 0][ca] = wv0.x; Bs[nxt][ck + 1][ca] = wv0.y;
            Bs[nxt][ck + 2][ca] = wv0.z; Bs[nxt][ck + 3][ca] = wv0.w;
            Bs[nxt][ck + 0][cb] = wv1.x; Bs[nxt][ck + 1][cb] = wv1.y;
            Bs[nxt][ck + 2][cb] = wv1.z; Bs[nxt][ck + 3][cb] = wv1.w;
        }
        __syncthreads();
        cur ^= 1;
    }

    // Bias: single rounded add after the full K sum (matches "einsum + b").
    // Per warp, each row's 32 lanes store contiguous 512B — coalesced.
    const int c = col0 + lane * 4;
    const float4 bv = *reinterpret_cast<const float4*>(&bias[c]);
#pragma unroll
    for (int i = 0; i < 16; i++) {
        const int r = row0 + w * 16 + i;
        float4 o;
        o.x = __fadd_rn(acc[i][0], bv.x);
        o.y = __fadd_rn(acc[i][1], bv.y);
        o.z = __fadd_rn(acc[i][2], bv.z);
        o.w = __fadd_rn(acc[i][3], bv.w);
        *reinterpret_cast<float4*>(&g_I[(size_t)r * HID + c]) = o;
    }
}

// ---------------------------------------------------------------------------
// LIF scan: one thread per (b, h) neuron, sequential over t.
// mem = fma.rn(alpha, mem, I); spike = (mem >= 1); hard reset.
// Unroll 16 for MLP=16.
// ---------------------------------------------------------------------------
__global__ __launch_bounds__(128)
void snn_scan_kernel(float* __restrict__ spikes,     // [B, T, H]
                     float* __restrict__ mem_final)  // [B, H]
{
    const int idx = blockIdx.x * blockDim.x + threadIdx.x;   // 0..65535
    const int b = idx >> 10;          // / HID
    const int h = idx & (HID - 1);

    const float* ip = g_I + (size_t)b * TSTEPS * HID + h;
    float* sp = spikes + (size_t)b * TSTEPS * HID + h;

    float mem = 0.0f;
    for (int t0 = 0; t0 < TSTEPS; t0 += 16) {
        float cur[16];
#pragma unroll
        for (int u = 0; u < 16; u++)
            cur[u] = __ldcg(ip + (size_t)(t0 + u) * HID);

        float sv[16];
#pragma unroll
        for (int u = 0; u < 16; u++) {
            mem = fmaf(ALPHA_F, mem, cur[u]);    // fused: one rounding
            const bool fire = (mem >= 1.0f);
            sv[u] = fire ? 1.0f : 0.0f;
            if (fire) mem = 0.0f;
        }
#pragma unroll
        for (int u = 0; u < 16; u++)
            sp[(size_t)(t0 + u) * HID] = sv[u];
    }
    mem_final[idx] = mem;
}

// ---------------------------------------------------------------------------
// Launch
// ---------------------------------------------------------------------------
extern "C" void kernel_launch(void* const* d_in, const int* in_sizes, int n_in,
                              void* d_out, int out_size)
{
    const float* x = (const float*)d_in[0];   // [B, T, IN_DIM]
    const float* W = (const float*)d_in[1];   // [HID, IN_DIM]
    const float* b = (const float*)d_in[2];   // [HID]

    float* out        = (float*)d_out;
    float* spikes     = out;                                  // [B, T, H]
    float* mem_final  = out + (size_t)BATCH * TSTEPS * HID;   // [B, H]

    dim3 ggrid(HID / BN, MTOT / BM);    // (8, 256)
    snn_gemm_kernel<<<ggrid, 256>>>(x, W, b);

    snn_scan_kernel<<<(BATCH * HID) / 128, 128>>>(spikes, mem_final);
}